// round 9
// baseline (speedup 1.0000x reference)
#include <cuda_runtime.h>

#define KMAX 21
#define GNUM 20
#define TILE 256
#define BT   672    // 21 warps: warp w owns plane k=w in phase 2
#define GRID 296
#define EPSF 1e-6f

__device__ float g_A[KMAX * GNUM];   // A[k*GNUM + g]
__device__ int   g_count;

__global__ void ms_init_kernel() {
    int t = threadIdx.x;
    if (t < KMAX * GNUM) g_A[t] = 0.0f;
    if (t == 0) g_count = 0;
}

// A[k,g] = sum_p d[p][k]*gt[g][p], with d = log2(p+eps)-log2(1-p+eps)
// (positive multiple of the reference's ln-based d -> same argmax).
// argmin_g ce[k,g] == argmax_g A[k,g] (log(1-p) term constant over g).
__global__ __launch_bounds__(BT, 2) void ms_accum_kernel(
    const void* bufA, const void* bufB, int n, float* __restrict__ out)
{
    __shared__ __align__(16) float sd[TILE * KMAX];
    __shared__ __align__(16) unsigned smask[TILE];
    __shared__ int s_last;

    const int tid  = threadIdx.x;
    const int lane = tid & 31;
    const int wid  = tid >> 5;

    // ---- inline buffer-identity probe (gt words are {0,1}) ----
    const unsigned wA = ((const unsigned*)bufA)[lane];
    const bool a_is_gt = (__ballot_sync(0xffffffffu, wA > 1u) == 0u);
    const float* seg = (const float*)(a_is_gt ? bufB : bufA);  // (N,21) f32
    const int*   gtp = (const int*)  (a_is_gt ? bufA : bufB);  // (21,N) {0,1}

    // ---- balanced contiguous chunk per block, 4-PIXEL ALIGNED so that
    // seg + base*21 floats is 16B aligned (base*84 bytes, 4|base -> 16|bytes).
    int begin = (int)(((long long)blockIdx.x * n) / GRID) & ~3;
    int end   = (int)(((long long)(blockIdx.x + 1) * n) / GRID) & ~3;
    if (blockIdx.x == GRID - 1) end = n;   // ragged tail handled by scalar path

    float acc[GNUM];
    #pragma unroll
    for (int g = 0; g < GNUM; g++) acc[g] = 0.0f;

    const bool maskOwner = (tid < TILE);

    // ---------- prologue: prefetch first tile into registers ----------
    int base = begin;
    int cnt  = min(TILE, end - base);
    float4 pf0 = {}, pf1 = {};
    unsigned mreg = 0;
    if (cnt > 0) {
        const int total4 = (cnt * KMAX) >> 2;
        const float4* src = (const float4*)(seg + (long long)base * KMAX);
        if (tid < total4)      pf0 = __ldg(src + tid);
        if (tid + BT < total4) pf1 = __ldg(src + tid + BT);
        if (maskOwner && tid < cnt) {
            unsigned m = 0;
            #pragma unroll
            for (int g = 0; g < GNUM; g++)
                m |= (__ldg(gtp + (long long)g * n + base + tid) != 0 ? 1u : 0u) << g;
            mreg = m;
        }
    }

    while (base < end) {
        // ---- phase 1: transform prefetched regs -> smem ----
        {
            const int total4 = (cnt * KMAX) >> 2;
            float4* dst = (float4*)sd;
            if (tid < total4) {
                float4 v = pf0, o;
                o.x = __log2f(v.x + EPSF) - __log2f(1.0f - v.x + EPSF);
                o.y = __log2f(v.y + EPSF) - __log2f(1.0f - v.y + EPSF);
                o.z = __log2f(v.z + EPSF) - __log2f(1.0f - v.z + EPSF);
                o.w = __log2f(v.w + EPSF) - __log2f(1.0f - v.w + EPSF);
                dst[tid] = o;
            }
            if (tid + BT < total4) {
                float4 v = pf1, o;
                o.x = __log2f(v.x + EPSF) - __log2f(1.0f - v.x + EPSF);
                o.y = __log2f(v.y + EPSF) - __log2f(1.0f - v.y + EPSF);
                o.z = __log2f(v.z + EPSF) - __log2f(1.0f - v.z + EPSF);
                o.w = __log2f(v.w + EPSF) - __log2f(1.0f - v.w + EPSF);
                dst[tid + BT] = o;
            }
            // scalar remainder (cnt*21 not /4): only on the last ragged tile
            for (int i = (total4 << 2) + tid; i < cnt * KMAX; i += BT) {
                float p = __ldg(seg + (long long)base * KMAX + i);
                sd[i] = __log2f(p + EPSF) - __log2f(1.0f - p + EPSF);
            }
            if (maskOwner) {
                if (tid >= cnt && tid < TILE) mreg = 0u;  // pad
                // ragged-tail masks for pixels not covered by prefetch
                if (tid < cnt && base + tid >= begin && cnt != TILE && 0) {}
                smask[tid] = (tid < cnt) ? mreg : 0u;
            }
            // ragged tile: mask prefetch above only ran when tid<cnt of the
            // *previous* prefetch, which used ncnt -> consistent (see below).
        }
        __syncthreads();

        // ---- prefetch NEXT tile while phase 2 computes ----
        const int nbase = base + TILE;
        const int ncnt  = min(TILE, end - nbase);
        if (nbase < end) {
            const int total4 = (ncnt * KMAX) >> 2;
            const float4* src = (const float4*)(seg + (long long)nbase * KMAX);
            if (tid < total4)      pf0 = __ldg(src + tid);
            if (tid + BT < total4) pf1 = __ldg(src + tid + BT);
            if (maskOwner) {
                if (tid < ncnt) {
                    unsigned m = 0;
                    #pragma unroll
                    for (int g = 0; g < GNUM; g++)
                        m |= (__ldg(gtp + (long long)g * n + nbase + tid) != 0 ? 1u : 0u) << g;
                    mreg = m;
                } else {
                    mreg = 0u;
                }
            }
        }

        // ---- phase 2: warp k, lane owns TILE/32 pixels; 20 reg accs ----
        // sd[p*21+k]: bank (lane*21+k)%32, 21 coprime 32 -> conflict-free.
        {
            const int k = wid;
            if (cnt == TILE) {
                const float* dbase = sd + lane * KMAX + k;
                #pragma unroll
                for (int j = 0; j < TILE / 32; j++) {
                    const float d = dbase[j * 32 * KMAX];
                    const unsigned m = smask[lane + j * 32];
                    #pragma unroll
                    for (int g = 0; g < GNUM; g++)
                        if (m & (1u << g)) acc[g] += d;
                }
            } else {
                for (int p = lane; p < cnt; p += 32) {
                    const float d = sd[p * KMAX + k];
                    const unsigned m = smask[p];
                    #pragma unroll
                    for (int g = 0; g < GNUM; g++)
                        if (m & (1u << g)) acc[g] += d;
                }
            }
        }
        __syncthreads();

        base = nbase;
        cnt  = ncnt;
    }

    // ---- warp butterfly + one atomic per (k,g) per block ----
    {
        #pragma unroll
        for (int g = 0; g < GNUM; g++) {
            float v = acc[g];
            #pragma unroll
            for (int off = 16; off > 0; off >>= 1)
                v += __shfl_xor_sync(0xffffffffu, v, off);
            if (lane == 0) atomicAdd(&g_A[wid * GNUM + g], v);
        }
    }

    // ---- last block finalizes (ticket) ----
    __threadfence();
    if (tid == 0)
        s_last = (atomicAdd(&g_count, 1) == GRID - 1) ? 1 : 0;
    __syncthreads();
    if (s_last && tid < KMAX) {
        const volatile float* A = g_A;
        float best = A[tid * GNUM + 0];
        int bi = 0;
        #pragma unroll
        for (int g = 1; g < GNUM; g++) {
            float v = A[tid * GNUM + g];
            if (v > best) { best = v; bi = g; }  // FIRST max == first min of ce
        }
        out[tid] = (float)bi;   // output compared as float32
    }
}

extern "C" void kernel_launch(void* const* d_in, const int* in_sizes, int n_in,
                              void* d_out, int out_size) {
    int maxSize = 0;
    for (int i = 0; i < n_in; i++)
        if (in_sizes[i] > maxSize) maxSize = in_sizes[i];
    int idxA = -1, idxB = -1;
    for (int i = 0; i < n_in; i++) {
        if (in_sizes[i] == maxSize) {
            if (idxA < 0) idxA = i;
            else if (idxB < 0) idxB = i;
        }
    }
    if (idxB < 0) idxB = idxA;

    const void* bufA = d_in[idxA];
    const void* bufB = d_in[idxB];
    const int n = maxSize / KMAX;
    float* out = (float*)d_out;

    ms_init_kernel<<<1, 512>>>();
    ms_accum_kernel<<<GRID, BT>>>(bufA, bufB, n, out);
    (void)out_size;
}

// round 10
// speedup vs baseline: 1.0831x; 1.0831x over previous
#include <cuda_runtime.h>
#include <cstdint>

#define KMAX 21
#define GNUM 20
#define TILE 256
#define BT   672                        // 21 warps; warp w owns plane k=w
#define GRID 296
#define EPSF 1e-6f

#define SEG_TILE_F (TILE * KMAX)        // 5376 floats
#define SEG_TILE_B (SEG_TILE_F * 4)     // 21504 B
#define GT_TILE_B  (GNUM * TILE * 4)    // 20480 B
#define STAGE_B    (SEG_TILE_B + GT_TILE_B)   // 41984 B
#define SMEM_TOTAL (2 * STAGE_B + TILE * 4 + 16)

__device__ float g_A[KMAX * GNUM];      // A[k*GNUM+g]
__device__ int   g_count;

__global__ void ms_init_kernel() {
    int t = threadIdx.x;
    if (t < KMAX * GNUM) g_A[t] = 0.0f;
    if (t == 0) g_count = 0;
}

__device__ __forceinline__ void cpasync16(uint32_t dst, const void* src) {
    asm volatile("cp.async.cg.shared.global [%0], [%1], 16;"
                 :: "r"(dst), "l"(src));
}
__device__ __forceinline__ void cp_commit() {
    asm volatile("cp.async.commit_group;");
}
__device__ __forceinline__ void cp_wait1() {
    asm volatile("cp.async.wait_group 1;");
}

// A[k,g] = sum_p d[p,k]*gt[g,p], d = log2(p+eps)-log2(1-p+eps)
// (positive multiple of reference's ln-based d -> same argmax).
// argmin_g ce[k,g] == argmax_g A[k,g].
__global__ __launch_bounds__(BT, 2) void ms_accum_kernel(
    const void* bufA, const void* bufB, int n, float* __restrict__ out)
{
    extern __shared__ __align__(16) char smem[];
    unsigned* smask = (unsigned*)(smem + 2 * STAGE_B);
    int* s_last = (int*)(smem + 2 * STAGE_B + TILE * 4);

    const int tid  = threadIdx.x;
    const int lane = tid & 31;
    const int wid  = tid >> 5;

    // ---- buffer-identity probe (gt words are {0,1}) ----
    const unsigned wA = ((const unsigned*)bufA)[lane];
    const bool a_is_gt = (__ballot_sync(0xffffffffu, wA > 1u) == 0u);
    const float* seg = (const float*)(a_is_gt ? bufB : bufA);  // (N,21) f32
    const int*   gtp = (const int*)  (a_is_gt ? bufA : bufB);  // (21,N) {0,1}

    // ---- balanced, 4-pixel-aligned contiguous chunk per block ----
    int begin = (int)(((long long)blockIdx.x * n) / GRID) & ~3;
    int end   = (int)(((long long)(blockIdx.x + 1) * n) / GRID) & ~3;
    if (blockIdx.x == GRID - 1) end = n;
    const int nTiles = (end - begin + TILE - 1) / TILE;

    const uint32_t smem_u32 = (uint32_t)__cvta_generic_to_shared(smem);

    // ---- prefetch of tile t into stage (t&1) via cp.async ----
    auto prefetch = [&](int t) {
        if (t < nTiles) {
            const int base = begin + t * TILE;
            const int cnt  = min(TILE, end - base);
            const uint32_t segd = smem_u32 + (t & 1) * STAGE_B;
            const uint32_t gtd  = segd + SEG_TILE_B;
            // seg: ceil(cnt*21/4) 16B chunks; clamp at global end
            const int totF = cnt * KMAX;
            int nch = (totF + 3) >> 2;
            int rem = 0;
            if (base + cnt == n && (totF & 3)) { nch = totF >> 2; rem = totF & 3; }
            const float* sbase = seg + (long long)base * KMAX;
            for (int c = tid; c < nch; c += BT)
                cpasync16(segd + c * 16, sbase + c * 4);
            if (tid < rem) {  // <=3 scalar floats, last tile of last block only
                float v = __ldg(sbase + nch * 4 + tid);
                *(float*)(smem + (t & 1) * STAGE_B + (nch * 4 + tid) * 4) = v;
            }
            // gt: 20 planes x ceil(cnt/4) chunks (overreads stay in gt buffer)
            const int npx4 = (cnt + 3) >> 2;
            for (int c = tid; c < GNUM * (TILE / 4); c += BT) {
                const int g = c >> 6, c6 = c & 63;
                if (c6 < npx4)
                    cpasync16(gtd + (g * TILE + c6 * 4) * 4,
                              gtp + (long long)g * n + base + c6 * 4);
            }
        }
        cp_commit();   // commit each slot (possibly empty) to keep count
    };

    float acc[GNUM];
    #pragma unroll
    for (int g = 0; g < GNUM; g++) acc[g] = 0.0f;

    prefetch(0);
    prefetch(1);

    for (int t = 0; t < nTiles; t++) {
        const int st   = t & 1;
        const int base = begin + t * TILE;
        const int cnt  = min(TILE, end - base);

        cp_wait1();
        __syncthreads();                       // stage st data visible to all

        // ---- masks from smem gt (LDS, conflict-free) ----
        if (tid < TILE) {
            unsigned m = 0;
            if (tid < cnt) {
                const int* gts = (const int*)(smem + st * STAGE_B + SEG_TILE_B);
                #pragma unroll
                for (int g = 0; g < GNUM; g++)
                    m |= (gts[g * TILE + tid] != 0 ? 1u : 0u) << g;
            }
            smask[tid] = m;
        }
        __syncthreads();                       // masks ready

        // ---- phase 2: warp k computes d inline + 20 predicated adds ----
        {
            const int k = wid;
            const float* segs = (const float*)(smem + st * STAGE_B);
            #pragma unroll
            for (int j = 0; j < TILE / 32; j++) {
                const int p = lane + 32 * j;
                const float pr = segs[p * KMAX + k];   // bank: 21 coprime 32
                const float d = __log2f(pr + EPSF) - __log2f(1.0f - pr + EPSF);
                const unsigned m = smask[p];           // 0 for p >= cnt
                #pragma unroll
                for (int g = 0; g < GNUM; g++)
                    if (m & (1u << g)) acc[g] += d;
            }
        }
        __syncthreads();                       // done reading stage st + smask

        prefetch(t + 2);                       // refill stage st
    }

    // ---- warp butterfly + one atomic per (k,g) per block ----
    #pragma unroll
    for (int g = 0; g < GNUM; g++) {
        float v = acc[g];
        #pragma unroll
        for (int off = 16; off > 0; off >>= 1)
            v += __shfl_xor_sync(0xffffffffu, v, off);
        if (lane == 0) atomicAdd(&g_A[wid * GNUM + g], v);
    }

    // ---- last block finalizes (ticket) ----
    __threadfence();
    if (tid == 0)
        *s_last = (atomicAdd(&g_count, 1) == GRID - 1) ? 1 : 0;
    __syncthreads();
    if (*s_last && tid < KMAX) {
        const volatile float* A = g_A;
        float best = A[tid * GNUM + 0];
        int bi = 0;
        #pragma unroll
        for (int g = 1; g < GNUM; g++) {
            float v = A[tid * GNUM + g];
            if (v > best) { best = v; bi = g; }   // FIRST max == first min of ce
        }
        out[tid] = (float)bi;    // output compared as float32
    }
}

extern "C" void kernel_launch(void* const* d_in, const int* in_sizes, int n_in,
                              void* d_out, int out_size) {
    int maxSize = 0;
    for (int i = 0; i < n_in; i++)
        if (in_sizes[i] > maxSize) maxSize = in_sizes[i];
    int idxA = -1, idxB = -1;
    for (int i = 0; i < n_in; i++) {
        if (in_sizes[i] == maxSize) {
            if (idxA < 0) idxA = i;
            else if (idxB < 0) idxB = i;
        }
    }
    if (idxB < 0) idxB = idxA;

    const void* bufA = d_in[idxA];
    const void* bufB = d_in[idxB];
    const int n = maxSize / KMAX;
    float* out = (float*)d_out;

    static int attr_done = 0;
    if (!attr_done) {
        cudaFuncSetAttribute(ms_accum_kernel,
                             cudaFuncAttributeMaxDynamicSharedMemorySize,
                             SMEM_TOTAL);
        attr_done = 1;
    }

    ms_init_kernel<<<1, 512>>>();
    ms_accum_kernel<<<GRID, BT, SMEM_TOTAL>>>(bufA, bufB, n, out);
    (void)out_size;
}

// round 11
// speedup vs baseline: 2.0894x; 1.9291x over previous
#include <cuda_runtime.h>
#include <cstdint>

#define KMAX 21
#define GNUM 20
#define TILE 256
#define BT   512            // 16 warps; warp w owns 8-pixel chunks w, w+16
#define GRID 296
#define EPSF 1e-6f
#define GT_ROW 260          // padded gt row stride (words): conflict-free LDS

#define SEG_TILE_F (TILE * KMAX)            // 5376 floats
#define SEG_TILE_B (SEG_TILE_F * 4)         // 21504 B
#define GT_TILE_B  (GNUM * GT_ROW * 4)      // 20800 B
#define STAGE_B    (SEG_TILE_B + GT_TILE_B) // 42304 B
#define SC_B       (KMAX * 24 * 4)          // 2016 B
#define SMEM_TOTAL (2 * STAGE_B + SC_B + 16)

__device__ float g_A[KMAX * GNUM];          // A[k*GNUM+g]
__device__ int   g_count;

__global__ void ms_init_kernel() {
    int t = threadIdx.x;
    if (t < KMAX * GNUM) g_A[t] = 0.0f;
    if (t == 0) g_count = 0;
}

__device__ __forceinline__ void cpasync16(uint32_t dst, const void* src) {
    asm volatile("cp.async.cg.shared.global [%0], [%1], 16;" :: "r"(dst), "l"(src));
}
__device__ __forceinline__ void cp_commit() { asm volatile("cp.async.commit_group;"); }
__device__ __forceinline__ void cp_wait1()  { asm volatile("cp.async.wait_group 1;"); }

__device__ __forceinline__ float dval(float p) {
    // log2 is a positive multiple of ln -> same argmax as reference.
    return __log2f(p + EPSF) - __log2f(1.0f - p + EPSF);
}

// C[16x8] += A[16x8(tf32)] x B[8x8(tf32)], standard Ampere fragment layouts.
#define MMA8(c, A, B) asm volatile( \
    "mma.sync.aligned.m16n8k8.row.col.f32.tf32.tf32.f32 " \
    "{%0,%1,%2,%3}, {%4,%5,%6,%7}, {%8,%9}, {%0,%1,%2,%3};" \
    : "+f"((c)[0]), "+f"((c)[1]), "+f"((c)[2]), "+f"((c)[3]) \
    : "r"((A)[0]), "r"((A)[1]), "r"((A)[2]), "r"((A)[3]), \
      "r"((B)[0]), "r"((B)[1]))

// A[k,g] = sum_p d[p,k]*gt[g,p] computed as split-K GEMM on the MMA pipe.
// argmin_g ce[k,g] == argmax_g A[k,g] (log(1-p) term constant over g).
__global__ __launch_bounds__(BT, 2) void ms_accum_kernel(
    const void* bufA, const void* bufB, int n, float* __restrict__ out)
{
    extern __shared__ __align__(16) char smem[];
    float* sC    = (float*)(smem + 2 * STAGE_B);          // [21][24]
    int*   s_last = (int*)(smem + 2 * STAGE_B + SC_B);

    const int tid  = threadIdx.x;
    const int lane = tid & 31;
    const int wid  = tid >> 5;
    const int tig  = lane & 3;     // thread-in-group (k-col / c-col pairs)
    const int gid  = lane >> 2;    // group id (row)

    // ---- buffer-identity probe (gt words are {0,1}) ----
    const unsigned wA = ((const unsigned*)bufA)[lane];
    const bool a_is_gt = (__ballot_sync(0xffffffffu, wA > 1u) == 0u);
    const float* seg = (const float*)(a_is_gt ? bufB : bufA);  // (N,21) f32
    const int*   gtp = (const int*)  (a_is_gt ? bufA : bufB);  // (21,N) {0,1}

    // ---- tile-granular balanced split ----
    const int totTiles = (n + TILE - 1) / TILE;
    const int t0 = (int)(((long long)blockIdx.x * totTiles) / GRID);
    const int t1 = (int)(((long long)(blockIdx.x + 1) * totTiles) / GRID);
    const int nT = t1 - t0;

    for (int i = tid; i < KMAX * 24; i += BT) sC[i] = 0.0f;

    const uint32_t smem_u32 = (uint32_t)__cvta_generic_to_shared(smem);

    auto prefetch = [&](int t) {
        if (t < nT) {
            const int base = (t0 + t) * TILE;
            const int cnt  = min(TILE, n - base);
            const uint32_t segd = smem_u32 + (t & 1) * STAGE_B;
            const uint32_t gtd  = segd + SEG_TILE_B;
            // seg: full 16B chunks (base is 256-multiple -> 16B aligned)
            const int sfull = (cnt * KMAX) >> 2;
            const int srem  = (cnt * KMAX) & 3;
            const float* sb = seg + (long long)base * KMAX;
            for (int c = tid; c < sfull; c += BT)
                cpasync16(segd + c * 16, sb + c * 4);
            if (tid < srem)   // never for n mult of 256; kept for generality
                *(float*)(smem + (t & 1) * STAGE_B + (sfull * 4 + tid) * 4) =
                    __ldg(sb + sfull * 4 + tid);
            if (cnt < TILE)   // zero seg pad (finite d, killed by B=0)
                for (int i = cnt * KMAX + tid; i < TILE * KMAX; i += BT)
                    *(float*)(smem + (t & 1) * STAGE_B + i * 4) = 0.0f;
            // gt: 20 planes x full 4-px chunks into padded rows
            const int cfull = cnt >> 2;
            for (int c = tid; c < GNUM * (TILE / 4); c += BT) {
                const int g = c >> 6, c6 = c & 63;
                if (c6 < cfull)
                    cpasync16(gtd + (g * GT_ROW + c6 * 4) * 4,
                              gtp + (long long)g * n + base + c6 * 4);
            }
            if (cnt < TILE || (cnt & 3)) {  // ragged: scalar + zero pad
                const int tailw = TILE - cfull * 4;
                for (int i = tid; i < GNUM * tailw; i += BT) {
                    const int g = i / tailw, p = cfull * 4 + i % tailw;
                    const int v = (p < cnt)
                        ? __ldg(gtp + (long long)g * n + base + p) : 0;
                    *(int*)(smem + (t & 1) * STAGE_B + SEG_TILE_B
                            + (g * GT_ROW + p) * 4) = v;
                }
            }
        }
        cp_commit();
    };

    float acc[6][4];   // [mt*3+nt][c0..c3]
    #pragma unroll
    for (int i = 0; i < 6; i++)
        #pragma unroll
        for (int j = 0; j < 4; j++) acc[i][j] = 0.0f;

    prefetch(0);
    prefetch(1);

    for (int t = 0; t < nT; t++) {
        const int st = t & 1;
        cp_wait1();
        __syncthreads();

        const float* ss  = (const float*)(smem + st * STAGE_B);
        const int*   gts = (const int*)(smem + st * STAGE_B + SEG_TILE_B);

        #pragma unroll
        for (int cc = 0; cc < 2; cc++) {
            const int cb = (wid + cc * 16) * 8;   // chunk base pixel
            const int p0 = cb + tig, p1 = p0 + 4;

            // ---- A fragments: d computed inline (each (p,k) used once) ----
            uint32_t a0[4], a1[4];
            a0[0] = __float_as_uint(dval(ss[p0 * KMAX + gid]));
            a0[1] = __float_as_uint(dval(ss[p0 * KMAX + gid + 8]));
            a0[2] = __float_as_uint(dval(ss[p1 * KMAX + gid]));
            a0[3] = __float_as_uint(dval(ss[p1 * KMAX + gid + 8]));
            const int r2 = 16 + gid;              // rows 16..20 valid, 21..23 pad
            const int r2s = (r2 < KMAX) ? r2 : 0; // safe smem index
            float e0 = dval(ss[p0 * KMAX + r2s]);
            float e1 = dval(ss[p1 * KMAX + r2s]);
            if (r2 >= KMAX) { e0 = 0.0f; e1 = 0.0f; }
            a1[0] = __float_as_uint(e0);
            a1[1] = 0u;                           // rows 24..31: 0.0f
            a1[2] = __float_as_uint(e1);
            a1[3] = 0u;

            // ---- B fragments: gi as 0.0/1.0 (conflict-free via GT_ROW) ----
            uint32_t b[3][2];
            #pragma unroll
            for (int nt = 0; nt < 3; nt++) {
                const int nn = nt * 8 + gid;
                float f0 = 0.0f, f1 = 0.0f;
                if (nn < GNUM) {
                    f0 = (float)gts[nn * GT_ROW + p0];
                    f1 = (float)gts[nn * GT_ROW + p1];
                }
                b[nt][0] = __float_as_uint(f0);
                b[nt][1] = __float_as_uint(f1);
            }

            #pragma unroll
            for (int nt = 0; nt < 3; nt++) {
                MMA8(acc[nt],     a0, b[nt]);     // planes 0..15
                MMA8(acc[3 + nt], a1, b[nt]);     // planes 16..20
            }
        }
        __syncthreads();
        prefetch(t + 2);
    }

    // ---- C fragments -> smem (block reduce), then global atomics ----
    #pragma unroll
    for (int mt = 0; mt < 2; mt++) {
        #pragma unroll
        for (int nt = 0; nt < 3; nt++) {
            const float* c = acc[mt * 3 + nt];
            const int r0 = mt * 16 + gid, r1 = r0 + 8;
            const int c0 = nt * 8 + 2 * tig, c1 = c0 + 1;
            if (r0 < KMAX && c0 < GNUM) atomicAdd(&sC[r0 * 24 + c0], c[0]);
            if (r0 < KMAX && c1 < GNUM) atomicAdd(&sC[r0 * 24 + c1], c[1]);
            if (r1 < KMAX && c0 < GNUM) atomicAdd(&sC[r1 * 24 + c0], c[2]);
            if (r1 < KMAX && c1 < GNUM) atomicAdd(&sC[r1 * 24 + c1], c[3]);
        }
    }
    __syncthreads();
    for (int i = tid; i < KMAX * GNUM; i += BT)
        atomicAdd(&g_A[i], sC[(i / GNUM) * 24 + (i % GNUM)]);

    // ---- last block finalizes (ticket) ----
    __threadfence();
    if (tid == 0)
        *s_last = (atomicAdd(&g_count, 1) == GRID - 1) ? 1 : 0;
    __syncthreads();
    if (*s_last && tid < KMAX) {
        const volatile float* A = g_A;
        float best = A[tid * GNUM + 0];
        int bi = 0;
        #pragma unroll
        for (int g = 1; g < GNUM; g++) {
            float v = A[tid * GNUM + g];
            if (v > best) { best = v; bi = g; }   // FIRST max == first min of ce
        }
        out[tid] = (float)bi;    // output compared as float32
    }
}

extern "C" void kernel_launch(void* const* d_in, const int* in_sizes, int n_in,
                              void* d_out, int out_size) {
    int maxSize = 0;
    for (int i = 0; i < n_in; i++)
        if (in_sizes[i] > maxSize) maxSize = in_sizes[i];
    int idxA = -1, idxB = -1;
    for (int i = 0; i < n_in; i++) {
        if (in_sizes[i] == maxSize) {
            if (idxA < 0) idxA = i;
            else if (idxB < 0) idxB = i;
        }
    }
    if (idxB < 0) idxB = idxA;

    const void* bufA = d_in[idxA];
    const void* bufB = d_in[idxB];
    const int n = maxSize / KMAX;
    float* out = (float*)d_out;

    static int attr_done = 0;
    if (!attr_done) {
        cudaFuncSetAttribute(ms_accum_kernel,
                             cudaFuncAttributeMaxDynamicSharedMemorySize,
                             SMEM_TOTAL);
        attr_done = 1;
    }

    ms_init_kernel<<<1, 512>>>();
    ms_accum_kernel<<<GRID, BT, SMEM_TOTAL>>>(bufA, bufB, n, out);
    (void)out_size;
}

// round 12
// speedup vs baseline: 2.5529x; 1.2218x over previous
#include <cuda_runtime.h>
#include <cstdint>

#define KMAX 21
#define GNUM 20
#define WT   32                      // pixels per warp-tile
#define NW   8                       // warps per block
#define BT   (NW * 32)               // 256
#define GRID 296
#define EPSF 1e-6f

#define SEG_SL_F (WT * KMAX)         // 672 floats
#define SEG_SL_B (SEG_SL_F * 4)      // 2688 B (168 x 16B chunks)
#define GT_ROW_W 36                  // padded plane stride: 144B, 16B-aligned,
                                     // B-frag bank = (4*gid+tig)%32 -> conflict-free
#define GT_SL_B  (GNUM * GT_ROW_W * 4)   // 2880 B
#define SLICE_B  (SEG_SL_B + GT_SL_B)    // 5568 B
#define NSTAGE   2
#define SC_B     (KMAX * 24 * 4)
#define SMEM_TOTAL (NW * NSTAGE * SLICE_B + SC_B + 16)   // ~91 KB

__device__ float g_A[KMAX * GNUM];
__device__ int   g_count;

__global__ void ms_init_kernel() {
    int t = threadIdx.x;
    if (t < KMAX * GNUM) g_A[t] = 0.0f;
    if (t == 0) g_count = 0;
}

__device__ __forceinline__ void cpasync16(uint32_t dst, const void* src) {
    asm volatile("cp.async.cg.shared.global [%0], [%1], 16;" :: "r"(dst), "l"(src));
}
__device__ __forceinline__ void cp_commit() { asm volatile("cp.async.commit_group;"); }
__device__ __forceinline__ void cp_wait1()  { asm volatile("cp.async.wait_group 1;"); }

__device__ __forceinline__ float dval(float p) {
    // log2 = positive multiple of ln -> same argmax as reference.
    return __log2f(p + EPSF) - __log2f(1.0f - p + EPSF);
}

// C[16x8] += A[16x8 tf32] x B[8x8 tf32]; fragment layouts validated in R11.
#define MMA8(c, A, B) asm volatile( \
    "mma.sync.aligned.m16n8k8.row.col.f32.tf32.tf32.f32 " \
    "{%0,%1,%2,%3}, {%4,%5,%6,%7}, {%8,%9}, {%0,%1,%2,%3};" \
    : "+f"((c)[0]), "+f"((c)[1]), "+f"((c)[2]), "+f"((c)[3]) \
    : "r"((A)[0]), "r"((A)[1]), "r"((A)[2]), "r"((A)[3]), \
      "r"((B)[0]), "r"((B)[1]))

// A[k,g] = sum_p d[p,k]*gt[g,p] as split-K GEMM; each warp is a fully
// autonomous cp.async double-buffered pipeline over its own pixel range
// (no cross-warp data sharing -> no per-tile block barriers).
__global__ __launch_bounds__(BT, 2) void ms_accum_kernel(
    const void* bufA, const void* bufB, int n, float* __restrict__ out)
{
    extern __shared__ __align__(16) char smem[];
    float* sC     = (float*)(smem + NW * NSTAGE * SLICE_B);
    int*   s_last = (int*)(smem + NW * NSTAGE * SLICE_B + SC_B);

    const int tid  = threadIdx.x;
    const int lane = tid & 31;
    const int wid  = tid >> 5;
    const int tig  = lane & 3;
    const int gid  = lane >> 2;

    // ---- buffer-identity probe (gt words are {0,1}) ----
    const unsigned wA = ((const unsigned*)bufA)[lane];
    const bool a_is_gt = (__ballot_sync(0xffffffffu, wA > 1u) == 0u);
    const float* seg = (const float*)(a_is_gt ? bufB : bufA);  // (N,21) f32
    const int*   gtp = (const int*)  (a_is_gt ? bufA : bufB);  // (21,N) {0,1}

    for (int i = tid; i < KMAX * 24; i += BT) sC[i] = 0.0f;
    __syncthreads();                         // sC zeroed before any epilogue

    // ---- balanced warp-tile range for this warp ----
    const int gw   = blockIdx.x * NW + wid;
    const int GW   = GRID * NW;
    const int totT = (n + WT - 1) / WT;
    const int w0 = (int)(((long long)gw * totT) / GW);
    const int w1 = (int)(((long long)(gw + 1) * totT) / GW);

    char* mySl = smem + wid * NSTAGE * SLICE_B;

    auto prefetch = [&](int t) {
        if (t < w1) {
            const int base = t * WT;
            const int cnt  = min(WT, n - base);
            char* sl = mySl + (t & 1) * SLICE_B;
            const uint32_t segd = (uint32_t)__cvta_generic_to_shared(sl);
            const uint32_t gtd  = segd + SEG_SL_B;
            if (cnt == WT) {
                const float* sb = seg + (long long)base * KMAX;  // 16B-aligned
                for (int c = lane; c < SEG_SL_B / 16; c += 32)   // 168 chunks
                    cpasync16(segd + c * 16, sb + c * 4);
                for (int c = lane; c < GNUM * (WT / 4); c += 32) { // 160 chunks
                    const int g = c >> 3, ch = c & 7;
                    cpasync16(gtd + (g * GT_ROW_W + ch * 4) * 4,
                              gtp + (long long)g * n + base + ch * 4);
                }
            } else {
                // ragged last tile: scalar LDG+STS, zero-pad (B=0 kills pads)
                for (int i = lane; i < SEG_SL_F; i += 32) {
                    float v = (i < cnt * KMAX)
                        ? __ldg(seg + (long long)base * KMAX + i) : 0.5f;
                    *(float*)(sl + i * 4) = v;
                }
                for (int i = lane; i < GNUM * WT; i += 32) {
                    const int g = i >> 5, p = i & 31;
                    const int v = (p < cnt)
                        ? __ldg(gtp + (long long)g * n + base + p) : 0;
                    *(int*)(sl + SEG_SL_B + (g * GT_ROW_W + p) * 4) = v;
                }
            }
        }
        cp_commit();          // unconditional: keeps group count consistent
    };

    float acc[6][4];
    #pragma unroll
    for (int i = 0; i < 6; i++)
        #pragma unroll
        for (int j = 0; j < 4; j++) acc[i][j] = 0.0f;

    prefetch(w0);
    prefetch(w0 + 1);

    for (int t = w0; t < w1; t++) {
        cp_wait1();
        __syncwarp();                        // cross-lane visibility of stage

        const char*  sl  = mySl + (t & 1) * SLICE_B;
        const float* ss  = (const float*)sl;
        const int*   gts = (const int*)(sl + SEG_SL_B);

        #pragma unroll
        for (int ch = 0; ch < WT / 8; ch++) {
            const int p0 = ch * 8 + tig, p1 = p0 + 4;

            // A frags: d computed inline, each (p,k) exactly once
            uint32_t a0[4], a1[4];
            a0[0] = __float_as_uint(dval(ss[p0 * KMAX + gid]));
            a0[1] = __float_as_uint(dval(ss[p0 * KMAX + gid + 8]));
            a0[2] = __float_as_uint(dval(ss[p1 * KMAX + gid]));
            a0[3] = __float_as_uint(dval(ss[p1 * KMAX + gid + 8]));
            const int r2 = 16 + gid;
            const int r2s = (r2 < KMAX) ? r2 : 0;
            float e0 = dval(ss[p0 * KMAX + r2s]);
            float e1 = dval(ss[p1 * KMAX + r2s]);
            if (r2 >= KMAX) { e0 = 0.0f; e1 = 0.0f; }
            a1[0] = __float_as_uint(e0);
            a1[1] = 0u;
            a1[2] = __float_as_uint(e1);
            a1[3] = 0u;

            // B frags: gi as 0.0/1.0; stride 36 words -> conflict-free
            uint32_t b[3][2];
            #pragma unroll
            for (int nt = 0; nt < 3; nt++) {
                const int nn = nt * 8 + gid;
                float f0 = 0.0f, f1 = 0.0f;
                if (nn < GNUM) {
                    f0 = (float)gts[nn * GT_ROW_W + p0];
                    f1 = (float)gts[nn * GT_ROW_W + p1];
                }
                b[nt][0] = __float_as_uint(f0);
                b[nt][1] = __float_as_uint(f1);
            }

            #pragma unroll
            for (int nt = 0; nt < 3; nt++) {
                MMA8(acc[nt],     a0, b[nt]);   // planes 0..15
                MMA8(acc[3 + nt], a1, b[nt]);   // planes 16..20
            }
        }
        __syncwarp();                        // all lanes done before overwrite
        prefetch(t + 2);
    }

    // ---- C frags -> smem block reduce ----
    #pragma unroll
    for (int mt = 0; mt < 2; mt++) {
        #pragma unroll
        for (int nt = 0; nt < 3; nt++) {
            const float* c = acc[mt * 3 + nt];
            const int r0 = mt * 16 + gid, r1 = r0 + 8;
            const int c0 = nt * 8 + 2 * tig, c1 = c0 + 1;
            if (r0 < KMAX && c0 < GNUM) atomicAdd(&sC[r0 * 24 + c0], c[0]);
            if (r0 < KMAX && c1 < GNUM) atomicAdd(&sC[r0 * 24 + c1], c[1]);
            if (r1 < KMAX && c0 < GNUM) atomicAdd(&sC[r1 * 24 + c0], c[2]);
            if (r1 < KMAX && c1 < GNUM) atomicAdd(&sC[r1 * 24 + c1], c[3]);
        }
    }
    __syncthreads();
    for (int i = tid; i < KMAX * GNUM; i += BT)
        atomicAdd(&g_A[i], sC[(i / GNUM) * 24 + (i % GNUM)]);

    // ---- last block finalizes (ticket) ----
    __threadfence();
    if (tid == 0)
        *s_last = (atomicAdd(&g_count, 1) == GRID - 1) ? 1 : 0;
    __syncthreads();
    if (*s_last && tid < KMAX) {
        const volatile float* A = g_A;
        float best = A[tid * GNUM + 0];
        int bi = 0;
        #pragma unroll
        for (int g = 1; g < GNUM; g++) {
            float v = A[tid * GNUM + g];
            if (v > best) { best = v; bi = g; }  // FIRST max == first min of ce
        }
        out[tid] = (float)bi;                    // output compared as float32
    }
}

extern "C" void kernel_launch(void* const* d_in, const int* in_sizes, int n_in,
                              void* d_out, int out_size) {
    int maxSize = 0;
    for (int i = 0; i < n_in; i++)
        if (in_sizes[i] > maxSize) maxSize = in_sizes[i];
    int idxA = -1, idxB = -1;
    for (int i = 0; i < n_in; i++) {
        if (in_sizes[i] == maxSize) {
            if (idxA < 0) idxA = i;
            else if (idxB < 0) idxB = i;
        }
    }
    if (idxB < 0) idxB = idxA;

    const void* bufA = d_in[idxA];
    const void* bufB = d_in[idxB];
    const int n = maxSize / KMAX;
    float* out = (float*)d_out;

    static int attr_done = 0;
    if (!attr_done) {
        cudaFuncSetAttribute(ms_accum_kernel,
                             cudaFuncAttributeMaxDynamicSharedMemorySize,
                             SMEM_TOTAL);
        attr_done = 1;
    }

    ms_init_kernel<<<1, 512>>>();
    ms_accum_kernel<<<GRID, BT, SMEM_TOTAL>>>(bufA, bufB, n, out);
    (void)out_size;
}